// round 6
// baseline (speedup 1.0000x reference)
#include <cuda_runtime.h>
#include <math.h>

#define SS 1024
#define CA 1024
#define CS 512
#define NH 16

// ---------------- scratch (static __device__, no allocs) ----------------
__device__ float d_an[SS*CA];
__device__ float d_sn[SS*CS];
__device__ float d_P1[SS*CA];
__device__ float d_P2[SS*CA];
__device__ float d_a1[SS*CA];
__device__ float d_Q [SS*CA];
__device__ float d_KVG[SS*3*CA];
__device__ float d_B [NH*SS*SS];   // pair bias, flat [i,j,h] == [h,x,y]
__device__ float d_Sc[NH*SS*SS];   // scores [h,x,y]
__device__ float d_M [NH*SS];
__device__ float d_Zi[NH*SS];      // 1/Z
__device__ float d_GO[SS*CA];
__device__ float d_A2[SS*CA];
__device__ float d_SD[SS*CA];

// ---------------- fast exp / sigmoid (FMA-only, no MUFU) ----------------
__device__ __forceinline__ float fexp(float x) {
    float y = x * 1.44269504088896341f;
    y = fminf(fmaxf(y, -120.f), 126.f);
    float t = y + 12582912.f;
    int   i = __float_as_int(t) - 0x4B400000;
    float f = y - (t - 12582912.f);
    float p = 1.3333558e-3f;
    p = fmaf(p, f, 9.6181291e-3f);
    p = fmaf(p, f, 5.5504109e-2f);
    p = fmaf(p, f, 2.4022651e-1f);
    p = fmaf(p, f, 6.9314718e-1f);
    p = fmaf(p, f, 1.0f);
    return p * __int_as_float((i + 127) << 23);
}
__device__ __forceinline__ float fsig(float v) { return 1.f / (1.f + fexp(-v)); }

// ---------------- tf32 mma helpers ----------------
__device__ __forceinline__ unsigned cvt_tf32(float x) {
    unsigned r; asm("cvt.rna.tf32.f32 %0, %1;" : "=r"(r) : "f"(x)); return r;
}
__device__ __forceinline__ void split_tf32(float x, unsigned& hi, unsigned& lo) {
    hi = cvt_tf32(x);
    lo = cvt_tf32(x - __uint_as_float(hi));
}
__device__ __forceinline__ void mma8(float* d, const unsigned* a, const unsigned* b) {
    asm volatile(
        "mma.sync.aligned.m16n8k8.row.col.f32.tf32.tf32.f32 "
        "{%0,%1,%2,%3}, {%4,%5,%6,%7}, {%8,%9}, {%0,%1,%2,%3};"
        : "+f"(d[0]), "+f"(d[1]), "+f"(d[2]), "+f"(d[3])
        : "r"(a[0]), "r"(a[1]), "r"(a[2]), "r"(a[3]), "r"(b[0]), "r"(b[1]));
}

// ---------------- LayerNorm over rows ----------------
__global__ void ln_kernel(const float* __restrict__ x, const float* __restrict__ w,
                          float* __restrict__ y, int C) {
    int row = blockIdx.x;
    const float* xr = x + (long long)row * C;
    float*       yr = y + (long long)row * C;
    float s = 0.f, s2 = 0.f;
    for (int i = threadIdx.x; i < C; i += blockDim.x) { float v = xr[i]; s += v; s2 += v*v; }
    __shared__ float sh[64];
    #pragma unroll
    for (int o = 16; o; o >>= 1) { s += __shfl_xor_sync(~0u, s, o); s2 += __shfl_xor_sync(~0u, s2, o); }
    int wid = threadIdx.x >> 5, lid = threadIdx.x & 31;
    if (lid == 0) { sh[wid] = s; sh[wid + 32] = s2; }
    __syncthreads();
    if (threadIdx.x == 0) {
        float a = 0.f, b = 0.f; int nw = blockDim.x >> 5;
        for (int i = 0; i < nw; i++) { a += sh[i]; b += sh[i + 32]; }
        float mean = a / C;
        float var  = b / C - mean * mean;
        sh[0] = mean; sh[1] = rsqrtf(var + 1e-5f);
    }
    __syncthreads();
    float mean = sh[0], inv = sh[1];
    for (int i = threadIdx.x; i < C; i += blockDim.x) {
        float v = (xr[i] - mean) * inv;
        if (w) v *= w[i];
        yr[i] = v;
    }
}

// ---------------- z LayerNorm + bias projection: 1M rows of 64 -> 16 ----------------
__global__ __launch_bounds__(128) void zbias_kernel(
    const float* __restrict__ z, const float* __restrict__ pnw, const float* __restrict__ pnb,
    const float* __restrict__ bw, const float* __restrict__ bb, float* __restrict__ out) {
    __shared__ float zt[128 * 65];
    __shared__ float w[16][64];
    __shared__ float wn[64], wb[64], bbs[16];
    int t = threadIdx.x;
    for (int i = t; i < 16 * 64; i += 128) w[i >> 6][i & 63] = bw[i];
    for (int i = t; i < 64; i += 128) { wn[i] = pnw[i]; wb[i] = pnb[i]; }
    if (t < 16) bbs[t] = bb[t];
    long long r0 = (long long)blockIdx.x * 128;
    const float* zp = z + r0 * 64;
    #pragma unroll
    for (int it = 0; it < 16; it++) {
        int idx = it * 512 + t * 4;
        float4 v = *(const float4*)(zp + idx);
        int r = idx >> 6, c = idx & 63;
        float* dst = &zt[r * 65 + c];
        dst[0] = v.x; dst[1] = v.y; dst[2] = v.z; dst[3] = v.w;
    }
    __syncthreads();
    float x[64]; float s = 0.f;
    #pragma unroll
    for (int k = 0; k < 64; k++) { x[k] = zt[t * 65 + k]; s += x[k]; }
    float mean = s * (1.f / 64.f), v2 = 0.f;
    #pragma unroll
    for (int k = 0; k < 64; k++) { float d = x[k] - mean; v2 += d * d; }
    float inv = rsqrtf(v2 * (1.f / 64.f) + 1e-5f);
    #pragma unroll
    for (int k = 0; k < 64; k++) x[k] = (x[k] - mean) * inv * wn[k] + wb[k];
    float acc[16];
    #pragma unroll
    for (int h = 0; h < 16; h++) acc[h] = bbs[h];
    #pragma unroll
    for (int k = 0; k < 64; k++) {
        float xv = x[k];
        #pragma unroll
        for (int h = 0; h < 16; h++) acc[h] = fmaf(xv, w[h][k], acc[h]);
    }
    float* op = out + (r0 + t) * 16;
    #pragma unroll
    for (int h = 0; h < 16; h += 4)
        *(float4*)(op + h) = make_float4(acc[h], acc[h+1], acc[h+2], acc[h+3]);
}

// ---------------- 3xTF32 GEMM, pre-split fragment-major SMEM ----------------
// C = scale*(A·B^T) [+bias[n]] [+Cadd], A[M,K] lda, B[N,K] ldb, batch via blockIdx.z.
// 64x64 tile, BK=16, 128 threads (4 warps, 2x2); inner loop = pure LDS+HMMA.
__global__ __launch_bounds__(128) void gemm_tf32(
    const float* __restrict__ Ag, int lda, long long sA,
    const float* __restrict__ Bg, int ldb, long long sB,
    float* __restrict__ Cg, int ldc, long long sC,
    const float* __restrict__ bias,
    const float* __restrict__ CaddG, long long sAdd,
    int K, float scale) {
    const float* A = Ag + (long long)blockIdx.z * sA;
    const float* B = Bg + (long long)blockIdx.z * sB;
    float*       C = Cg + (long long)blockIdx.z * sC;
    const float* Cadd = CaddG ? CaddG + (long long)blockIdx.z * sAdd : nullptr;
    // fragment-major: [mtile][ks][lane][reg]
    __shared__ unsigned AH[4][2][32][4], AL[4][2][32][4];
    __shared__ unsigned BH[8][2][32][2], BL[8][2][32][2];
    int t = threadIdx.x;
    int lane = t & 31, wid = t >> 5;
    int wm = wid >> 1, wn = wid & 1;           // warp m-half / n-half
    int m0 = blockIdx.y * 64, n0 = blockIdx.x * 64;
    int lrow = t >> 2;                          // 0..31
    int lc4  = (t & 3) * 4;                     // 0,4,8,12
    // staging constants (per thread)
    const int sks   = lc4 >> 3;                 // k-subtile 0/1
    const int khalf = (lc4 >> 2) & 1;           // selects reg-pair
    float d[2][4][4] = {};
    const float* Ap0 = A + (long long)(m0 + lrow) * lda + lc4;
    const float* Ap1 = A + (long long)(m0 + lrow + 32) * lda + lc4;
    const float* Bp0 = B + (long long)(n0 + lrow) * ldb + lc4;
    const float* Bp1 = B + (long long)(n0 + lrow + 32) * ldb + lc4;
    float4 av0 = *(const float4*)(Ap0);
    float4 av1 = *(const float4*)(Ap1);
    float4 bv0 = *(const float4*)(Bp0);
    float4 bv1 = *(const float4*)(Bp1);
    for (int k0 = 0; k0 < K; k0 += 16) {
        __syncthreads();
        // ---- stage A rows lrow, lrow+32 ----
        #pragma unroll
        for (int half = 0; half < 2; half++) {
            int r = lrow + half * 32;
            const float* v = half ? &av1.x : &av0.x;
            int mt = r >> 4, rr = r & 15;
            int g = rr & 7;
            int reg = (rr >> 3) + (khalf << 1);
            #pragma unroll
            for (int e = 0; e < 4; e++) {
                unsigned hi, lo; split_tf32(v[e], hi, lo);
                AH[mt][sks][g * 4 + e][reg] = hi;
                AL[mt][sks][g * 4 + e][reg] = lo;
            }
        }
        // ---- stage B rows (cols) lrow, lrow+32 ----
        #pragma unroll
        for (int half = 0; half < 2; half++) {
            int n = lrow + half * 32;
            const float* v = half ? &bv1.x : &bv0.x;
            int nt = n >> 3, g = n & 7;
            #pragma unroll
            for (int e = 0; e < 4; e++) {
                unsigned hi, lo; split_tf32(v[e], hi, lo);
                BH[nt][sks][g * 4 + e][khalf] = hi;
                BL[nt][sks][g * 4 + e][khalf] = lo;
            }
        }
        __syncthreads();
        if (k0 + 16 < K) {
            av0 = *(const float4*)(Ap0 + k0 + 16);
            av1 = *(const float4*)(Ap1 + k0 + 16);
            bv0 = *(const float4*)(Bp0 + k0 + 16);
            bv1 = *(const float4*)(Bp1 + k0 + 16);
        }
        #pragma unroll
        for (int ks = 0; ks < 2; ks++) {
            uint4 xah[2], xal[2];
            uint2 xbh[4], xbl[4];
            #pragma unroll
            for (int mtl = 0; mtl < 2; mtl++) {
                xah[mtl] = *(const uint4*)AH[wm * 2 + mtl][ks][lane];
                xal[mtl] = *(const uint4*)AL[wm * 2 + mtl][ks][lane];
            }
            #pragma unroll
            for (int ntl = 0; ntl < 4; ntl++) {
                xbh[ntl] = *(const uint2*)BH[wn * 4 + ntl][ks][lane];
                xbl[ntl] = *(const uint2*)BL[wn * 4 + ntl][ks][lane];
            }
            #pragma unroll
            for (int mtl = 0; mtl < 2; mtl++)
                #pragma unroll
                for (int ntl = 0; ntl < 4; ntl++) {
                    mma8(d[mtl][ntl], (const unsigned*)&xah[mtl], (const unsigned*)&xbh[ntl]);
                    mma8(d[mtl][ntl], (const unsigned*)&xah[mtl], (const unsigned*)&xbl[ntl]);
                    mma8(d[mtl][ntl], (const unsigned*)&xal[mtl], (const unsigned*)&xbh[ntl]);
                }
        }
    }
    int g = lane >> 2, c = lane & 3;
    #pragma unroll
    for (int mtl = 0; mtl < 2; mtl++) {
        #pragma unroll
        for (int ntl = 0; ntl < 4; ntl++) {
            int row0 = m0 + wm * 32 + mtl * 16 + g;
            int col  = n0 + wn * 32 + ntl * 8 + 2 * c;
            #pragma unroll
            for (int half = 0; half < 2; half++) {
                int m = row0 + half * 8;
                float v0 = d[mtl][ntl][half * 2 + 0] * scale;
                float v1 = d[mtl][ntl][half * 2 + 1] * scale;
                if (bias) { v0 += bias[col]; v1 += bias[col + 1]; }
                if (Cadd) {
                    v0 += Cadd[(long long)m * ldc + col];
                    v1 += Cadd[(long long)m * ldc + col + 1];
                }
                *(float2*)(C + (long long)m * ldc + col) = make_float2(v0, v1);
            }
        }
    }
}

// ---------------- elementwise (float4 vectorized) ----------------
__global__ void a1_kernel(const float4* __restrict__ P1, const float4* __restrict__ P2,
                          const float4* __restrict__ an, float4* __restrict__ o) {
    int i = blockIdx.x * 256 + threadIdx.x;
    float4 p1 = P1[i], p2 = P2[i], av = an[i], r;
    r.x = fsig(fmaf(p1.x, av.x, p2.x));
    r.y = fsig(fmaf(p1.y, av.y, p2.y));
    r.z = fsig(fmaf(p1.z, av.z, p2.z));
    r.w = fsig(fmaf(p1.w, av.w, p2.w));
    o[i] = r;
}
__global__ void final_kernel(const float4* __restrict__ SD, const float4* __restrict__ A2,
                             float4* __restrict__ o) {
    int i = blockIdx.x * 256 + threadIdx.x;
    float4 sd = SD[i], a2 = A2[i], r;
    r.x = fsig(sd.x) * a2.x;
    r.y = fsig(sd.y) * a2.y;
    r.z = fsig(sd.z) * a2.z;
    r.w = fsig(sd.w) * a2.w;
    o[i] = r;
}

// ---------------- row softmax stats ----------------
__global__ __launch_bounds__(256) void stats_kernel(const float* __restrict__ Sc,
                                                    float* __restrict__ Mo, float* __restrict__ Zi) {
    long long row = blockIdx.x;
    const float* p = Sc + row * 1024;
    int t = threadIdx.x;
    float4 v = *(const float4*)(p + t * 4);
    float mx = fmaxf(fmaxf(v.x, v.y), fmaxf(v.z, v.w));
    __shared__ float sh[8];
    #pragma unroll
    for (int o = 16; o; o >>= 1) mx = fmaxf(mx, __shfl_xor_sync(~0u, mx, o));
    if ((t & 31) == 0) sh[t >> 5] = mx;
    __syncthreads();
    if (t == 0) { float m = sh[0]; for (int i = 1; i < 8; i++) m = fmaxf(m, sh[i]); sh[0] = m; }
    __syncthreads();
    mx = sh[0];
    float sum = fexp(v.x - mx) + fexp(v.y - mx) + fexp(v.z - mx) + fexp(v.w - mx);
    #pragma unroll
    for (int o = 16; o; o >>= 1) sum += __shfl_xor_sync(~0u, sum, o);
    __syncthreads();
    if ((t & 31) == 0) sh[t >> 5] = sum;
    __syncthreads();
    if (t == 0) { float s = 0.f; for (int i = 0; i < 8; i++) s += sh[i]; Mo[row] = mx; Zi[row] = 1.f / s; }
}

// ---------------- AV via 3xTF32, pre-split fragment staging ----------------
// GO[j,c] = sig(g)*sum_x E[x,j]*Zi[x]*V[x,c]; A[m=j][k=x]=E, B[n=c][k=x]=V*Zi.
__global__ __launch_bounds__(128) void av_tf32(
    const float* __restrict__ Sc, const float* __restrict__ Mx, const float* __restrict__ Zi,
    const float* __restrict__ KVG, float* __restrict__ GO) {
    int h = blockIdx.y;
    int j0 = blockIdx.x * 64;
    const float* Sch = Sc + (long long)h * (1 << 20);
    const float* Mh  = Mx + (h << 10);
    const float* Zh  = Zi + (h << 10);
    const float* Vh  = KVG + (long long)h * 196608 + 64;
    const float* Gh  = KVG + (long long)h * 196608 + 128;
    float*       GOh = GO + (long long)h * 65536;
    __shared__ unsigned EH[4][2][32][4], EL[4][2][32][4];
    __shared__ unsigned VH[8][2][32][2], VL[8][2][32][2];
    int t = threadIdx.x;
    int lane = t & 31, wid = t >> 5;
    int wm = wid >> 1, wn = wid & 1;
    float d[2][4][4] = {};
    for (int x0 = 0; x0 < 1024; x0 += 16) {
        __syncthreads();
        #pragma unroll
        for (int i = 0; i < 2; i++) {
            int idx = t + i * 128;
            int x  = idx >> 4;                  // 0..15 (k within tile)
            int c4 = (idx & 15) * 4;            // 0..60 (m / n within tile)
            int ks = x >> 3, kk = x & 7;
            int cc = kk & 3, khalf = kk >> 2;
            float m  = Mh[x0 + x];
            float rz = Zh[x0 + x];
            // E tile (A operand): rows j = c4..c4+3 at k=x
            {
                float4 e = *(const float4*)(Sch + (long long)(x0 + x) * 1024 + j0 + c4);
                e.x = fexp(e.x - m); e.y = fexp(e.y - m); e.z = fexp(e.z - m); e.w = fexp(e.w - m);
                int mt = c4 >> 4;
                int rrb = c4 & 15;
                int reg = (rrb >> 3) + (khalf << 1);
                const float* ev = &e.x;
                #pragma unroll
                for (int e4 = 0; e4 < 4; e4++) {
                    int g = (rrb + e4) & 7;
                    unsigned hi, lo; split_tf32(ev[e4], hi, lo);
                    EH[mt][ks][g * 4 + cc][reg] = hi;
                    EL[mt][ks][g * 4 + cc][reg] = lo;
                }
            }
            // V tile (B operand): cols ch = c4..c4+3 at k=x, scaled by Zi
            {
                float4 vv = *(const float4*)(Vh + (long long)(x0 + x) * 192 + c4);
                vv.x *= rz; vv.y *= rz; vv.z *= rz; vv.w *= rz;
                int nt = c4 >> 3;
                const float* pv = &vv.x;
                #pragma unroll
                for (int e4 = 0; e4 < 4; e4++) {
                    int g = (c4 + e4) & 7;
                    unsigned hi, lo; split_tf32(pv[e4], hi, lo);
                    VH[nt][ks][g * 4 + cc][khalf] = hi;
                    VL[nt][ks][g * 4 + cc][khalf] = lo;
                }
            }
        }
        __syncthreads();
        #pragma unroll
        for (int ks = 0; ks < 2; ks++) {
            uint4 xah[2], xal[2];
            uint2 xbh[4], xbl[4];
            #pragma unroll
            for (int mtl = 0; mtl < 2; mtl++) {
                xah[mtl] = *(const uint4*)EH[wm * 2 + mtl][ks][lane];
                xal[mtl] = *(const uint4*)EL[wm * 2 + mtl][ks][lane];
            }
            #pragma unroll
            for (int ntl = 0; ntl < 4; ntl++) {
                xbh[ntl] = *(const uint2*)VH[wn * 4 + ntl][ks][lane];
                xbl[ntl] = *(const uint2*)VL[wn * 4 + ntl][ks][lane];
            }
            #pragma unroll
            for (int mtl = 0; mtl < 2; mtl++)
                #pragma unroll
                for (int ntl = 0; ntl < 4; ntl++) {
                    mma8(d[mtl][ntl], (const unsigned*)&xah[mtl], (const unsigned*)&xbh[ntl]);
                    mma8(d[mtl][ntl], (const unsigned*)&xah[mtl], (const unsigned*)&xbl[ntl]);
                    mma8(d[mtl][ntl], (const unsigned*)&xal[mtl], (const unsigned*)&xbh[ntl]);
                }
        }
    }
    int g = lane >> 2, c = lane & 3;
    #pragma unroll
    for (int mtl = 0; mtl < 2; mtl++) {
        #pragma unroll
        for (int ntl = 0; ntl < 4; ntl++) {
            int j0r = j0 + wm * 32 + mtl * 16 + g;
            int cc  = wn * 32 + ntl * 8 + 2 * c;
            #pragma unroll
            for (int half = 0; half < 2; half++) {
                int j = j0r + half * 8;
                float g0 = fsig(Gh[(long long)j * 192 + cc]);
                float g1 = fsig(Gh[(long long)j * 192 + cc + 1]);
                float v0 = d[mtl][ntl][half * 2 + 0] * g0;
                float v1 = d[mtl][ntl][half * 2 + 1] * g1;
                *(float2*)(GOh + (long long)j * 64 + cc) = make_float2(v0, v1);
            }
        }
    }
}

// ---------------- driver ----------------
extern "C" void kernel_launch(void* const* d_in, const int* in_sizes, int n_in,
                              void* d_out, int out_size) {
    const float* a      = (const float*)d_in[0];
    const float* z      = (const float*)d_in[1];
    const float* s      = (const float*)d_in[2];
    const float* sn_w   = (const float*)d_in[3];
    const float* pb_w   = (const float*)d_in[4];
    const float* pb_b   = (const float*)d_in[5];
    const float* pn_w   = (const float*)d_in[6];
    const float* pnorm_w= (const float*)d_in[7];
    const float* pnorm_b= (const float*)d_in[8];
    const float* q_w    = (const float*)d_in[9];
    const float* q_b    = (const float*)d_in[10];
    const float* kvg_w  = (const float*)d_in[11];
    const float* bias_w = (const float*)d_in[12];
    const float* bias_b = (const float*)d_in[13];
    const float* attn_w = (const float*)d_in[14];
    const float* out_w  = (const float*)d_in[15];
    const float* out_b  = (const float*)d_in[16];
    float* out = (float*)d_out;

    float *an, *sn, *P1, *P2, *a1, *Q, *KVG, *Bm, *Sc, *Mx, *Zi, *GO, *A2, *SD;
    cudaGetSymbolAddress((void**)&an, d_an);
    cudaGetSymbolAddress((void**)&sn, d_sn);
    cudaGetSymbolAddress((void**)&P1, d_P1);
    cudaGetSymbolAddress((void**)&P2, d_P2);
    cudaGetSymbolAddress((void**)&a1, d_a1);
    cudaGetSymbolAddress((void**)&Q,  d_Q);
    cudaGetSymbolAddress((void**)&KVG,d_KVG);
    cudaGetSymbolAddress((void**)&Bm, d_B);
    cudaGetSymbolAddress((void**)&Sc, d_Sc);
    cudaGetSymbolAddress((void**)&Mx, d_M);
    cudaGetSymbolAddress((void**)&Zi, d_Zi);
    cudaGetSymbolAddress((void**)&GO, d_GO);
    cudaGetSymbolAddress((void**)&A2, d_A2);
    cudaGetSymbolAddress((void**)&SD, d_SD);

    // 1) LayerNorms
    ln_kernel<<<SS, 256>>>(a, nullptr, an, CA);
    ln_kernel<<<SS, 256>>>(s, sn_w,  sn, CS);

    // 2) P1 = sn@pb_w^T + pb_b ; P2 = sn@pn_w^T
    gemm_tf32<<<dim3(16,16,1), 128>>>(sn, CS, 0, pb_w, CS, 0, P1, CA, 0, pb_b, nullptr, 0, CS, 1.f);
    gemm_tf32<<<dim3(16,16,1), 128>>>(sn, CS, 0, pn_w, CS, 0, P2, CA, 0, nullptr, nullptr, 0, CS, 1.f);

    // 3) a1 = sigmoid(P1*an + P2)
    a1_kernel<<<1024, 256>>>((const float4*)P1, (const float4*)P2, (const float4*)an, (float4*)a1);

    // 4) Q and KVG projections
    gemm_tf32<<<dim3(16,16,1), 128>>>(a1, CA, 0, q_w,   CA, 0, Q,   CA,   0, q_b,    nullptr, 0, CA, 1.f);
    gemm_tf32<<<dim3(48,16,1), 128>>>(a1, CA, 0, kvg_w, CA, 0, KVG, 3*CA, 0, nullptr, nullptr, 0, CA, 1.f);

    // 5) pair bias from z (LN + projection), flat layout == [h,x,y]
    zbias_kernel<<<8192, 128>>>(z, pnorm_w, pnorm_b, bias_w, bias_b, Bm);

    // 6) scores Sc[h,x,y] = K[x]·Q[y]/64 + bias
    gemm_tf32<<<dim3(16,16,NH), 128>>>(KVG, 192, 196608, Q, 64, 65536,
                                       Sc, 1024, 1 << 20, nullptr, Bm, 1 << 20, 64, 1.f/64.f);

    // 7) softmax row stats
    stats_kernel<<<NH*SS, 256>>>(Sc, Mx, Zi);

    // 8) O = P^T V, gated by sigmoid(g); GO flat == [S,ca]
    av_tf32<<<dim3(16,16), 128>>>(Sc, Mx, Zi, KVG, GO);

    // 9) a2 = GO@attn_w^T ; SD = s@out_w^T + out_b
    gemm_tf32<<<dim3(16,16,1), 128>>>(GO, CA, 0, attn_w, CA, 0, A2, CA, 0, nullptr, nullptr, 0, CA, 1.f);
    gemm_tf32<<<dim3(16,16,1), 128>>>(s,  CS, 0, out_w,  CS, 0, SD, CA, 0, out_b,  nullptr, 0, CS, 1.f);

    // 10) out = sigmoid(SD) * a2
    final_kernel<<<1024, 256>>>((const float4*)SD, (const float4*)A2, (float4*)out);
}

// round 7
// speedup vs baseline: 1.0917x; 1.0917x over previous
#include <cuda_runtime.h>
#include <math.h>

#define SS 1024
#define CA 1024
#define CS 512
#define NH 16

// ---------------- scratch (static __device__, no allocs) ----------------
__device__ float d_an[SS*CA];
__device__ float d_sn[SS*CS];
__device__ float d_P1[SS*CA];
__device__ float d_P2[SS*CA];
__device__ float d_a1[SS*CA];
__device__ float d_Q [SS*CA];
__device__ float d_KVG[SS*3*CA];
__device__ float d_B [NH*SS*SS];   // pair bias, flat [i,j,h] == [h,x,y]
__device__ float d_Sc[NH*SS*SS];   // scores [h,x,y]
__device__ float d_M [NH*SS];
__device__ float d_Zi[NH*SS];      // 1/Z
__device__ float d_GO[SS*CA];
__device__ float d_A2[SS*CA];
__device__ float d_SD[SS*CA];

// ---------------- fast exp / sigmoid (FMA-only, no MUFU) ----------------
__device__ __forceinline__ float fexp(float x) {
    float y = x * 1.44269504088896341f;
    y = fminf(fmaxf(y, -120.f), 126.f);
    float t = y + 12582912.f;
    int   i = __float_as_int(t) - 0x4B400000;
    float f = y - (t - 12582912.f);
    float p = 1.3333558e-3f;
    p = fmaf(p, f, 9.6181291e-3f);
    p = fmaf(p, f, 5.5504109e-2f);
    p = fmaf(p, f, 2.4022651e-1f);
    p = fmaf(p, f, 6.9314718e-1f);
    p = fmaf(p, f, 1.0f);
    return p * __int_as_float((i + 127) << 23);
}
__device__ __forceinline__ float fsig(float v) { return 1.f / (1.f + fexp(-v)); }

// ---------------- tf32 mma helpers ----------------
__device__ __forceinline__ unsigned cvt_tf32(float x) {
    unsigned r; asm("cvt.rna.tf32.f32 %0, %1;" : "=r"(r) : "f"(x)); return r;
}
__device__ __forceinline__ void split_tf32(float x, unsigned& hi, unsigned& lo) {
    hi = cvt_tf32(x);
    lo = cvt_tf32(x - __uint_as_float(hi));
}
__device__ __forceinline__ void mma8(float* d, const unsigned* a, const unsigned* b) {
    asm volatile(
        "mma.sync.aligned.m16n8k8.row.col.f32.tf32.tf32.f32 "
        "{%0,%1,%2,%3}, {%4,%5,%6,%7}, {%8,%9}, {%0,%1,%2,%3};"
        : "+f"(d[0]), "+f"(d[1]), "+f"(d[2]), "+f"(d[3])
        : "r"(a[0]), "r"(a[1]), "r"(a[2]), "r"(a[3]), "r"(b[0]), "r"(b[1]));
}

// ---------------- LayerNorm over rows ----------------
__global__ void ln_kernel(const float* __restrict__ x, const float* __restrict__ w,
                          float* __restrict__ y, int C) {
    int row = blockIdx.x;
    const float* xr = x + (long long)row * C;
    float*       yr = y + (long long)row * C;
    float s = 0.f, s2 = 0.f;
    for (int i = threadIdx.x; i < C; i += blockDim.x) { float v = xr[i]; s += v; s2 += v*v; }
    __shared__ float sh[64];
    #pragma unroll
    for (int o = 16; o; o >>= 1) { s += __shfl_xor_sync(~0u, s, o); s2 += __shfl_xor_sync(~0u, s2, o); }
    int wid = threadIdx.x >> 5, lid = threadIdx.x & 31;
    if (lid == 0) { sh[wid] = s; sh[wid + 32] = s2; }
    __syncthreads();
    if (threadIdx.x == 0) {
        float a = 0.f, b = 0.f; int nw = blockDim.x >> 5;
        for (int i = 0; i < nw; i++) { a += sh[i]; b += sh[i + 32]; }
        float mean = a / C;
        float var  = b / C - mean * mean;
        sh[0] = mean; sh[1] = rsqrtf(var + 1e-5f);
    }
    __syncthreads();
    float mean = sh[0], inv = sh[1];
    for (int i = threadIdx.x; i < C; i += blockDim.x) {
        float v = (xr[i] - mean) * inv;
        if (w) v *= w[i];
        yr[i] = v;
    }
}

// ---------------- z LayerNorm + bias projection: 1M rows of 64 -> 16 ----------------
__global__ __launch_bounds__(128) void zbias_kernel(
    const float* __restrict__ z, const float* __restrict__ pnw, const float* __restrict__ pnb,
    const float* __restrict__ bw, const float* __restrict__ bb, float* __restrict__ out) {
    __shared__ float zt[128 * 65];
    __shared__ float w[16][64];
    __shared__ float wn[64], wb[64], bbs[16];
    int t = threadIdx.x;
    for (int i = t; i < 16 * 64; i += 128) w[i >> 6][i & 63] = bw[i];
    for (int i = t; i < 64; i += 128) { wn[i] = pnw[i]; wb[i] = pnb[i]; }
    if (t < 16) bbs[t] = bb[t];
    long long r0 = (long long)blockIdx.x * 128;
    const float* zp = z + r0 * 64;
    #pragma unroll
    for (int it = 0; it < 16; it++) {
        int idx = it * 512 + t * 4;
        float4 v = *(const float4*)(zp + idx);
        int r = idx >> 6, c = idx & 63;
        float* dst = &zt[r * 65 + c];
        dst[0] = v.x; dst[1] = v.y; dst[2] = v.z; dst[3] = v.w;
    }
    __syncthreads();
    float x[64]; float s = 0.f;
    #pragma unroll
    for (int k = 0; k < 64; k++) { x[k] = zt[t * 65 + k]; s += x[k]; }
    float mean = s * (1.f / 64.f), v2 = 0.f;
    #pragma unroll
    for (int k = 0; k < 64; k++) { float d = x[k] - mean; v2 += d * d; }
    float inv = rsqrtf(v2 * (1.f / 64.f) + 1e-5f);
    #pragma unroll
    for (int k = 0; k < 64; k++) x[k] = (x[k] - mean) * inv * wn[k] + wb[k];
    float acc[16];
    #pragma unroll
    for (int h = 0; h < 16; h++) acc[h] = bbs[h];
    #pragma unroll
    for (int k = 0; k < 64; k++) {
        float xv = x[k];
        #pragma unroll
        for (int h = 0; h < 16; h++) acc[h] = fmaf(xv, w[h][k], acc[h]);
    }
    float* op = out + (r0 + t) * 16;
    #pragma unroll
    for (int h = 0; h < 16; h += 4)
        *(float4*)(op + h) = make_float4(acc[h], acc[h+1], acc[h+2], acc[h+3]);
}

// ---------------- 3xTF32 GEMM, pre-split hi/lo planes, 256 threads ----------------
// C = scale*(A·B^T) [+bias[n]] [+Cadd]. 64x64 tile, BK=16, 8 warps (2x4), 32x16/warp.
__global__ __launch_bounds__(256) void gemm_tf32(
    const float* __restrict__ Ag, int lda, long long sA,
    const float* __restrict__ Bg, int ldb, long long sB,
    float* __restrict__ Cg, int ldc, long long sC,
    const float* __restrict__ bias,
    const float* __restrict__ CaddG, long long sAdd,
    int K, float scale) {
    const float* A = Ag + (long long)blockIdx.z * sA;
    const float* B = Bg + (long long)blockIdx.z * sB;
    float*       C = Cg + (long long)blockIdx.z * sC;
    const float* Cadd = CaddG ? CaddG + (long long)blockIdx.z * sAdd : nullptr;
    __shared__ unsigned AsH[64][17], AsL[64][17];
    __shared__ unsigned BsH[64][17], BsL[64][17];
    int t = threadIdx.x;
    int lane = t & 31, wid = t >> 5;
    int wm = wid >> 2, wn = wid & 3;       // 2 x 4 warp grid; warp tile 32(m) x 16(n)
    int g = lane >> 2, c = lane & 3;
    int m0 = blockIdx.y * 64, n0 = blockIdx.x * 64;
    int lrow = t >> 2;                      // 0..63
    int lc4  = (t & 3) * 4;                 // 0,4,8,12
    const float* Ap = A + (long long)(m0 + lrow) * lda + lc4;
    const float* Bp = B + (long long)(n0 + lrow) * ldb + lc4;
    float4 av = *(const float4*)Ap;
    float4 bv = *(const float4*)Bp;
    float d[2][2][4] = {};
    for (int k0 = 0; k0 < K; k0 += 16) {
        __syncthreads();
        {
            const float* pa = &av.x;
            const float* pb = &bv.x;
            #pragma unroll
            for (int e = 0; e < 4; e++) {
                unsigned hi, lo;
                split_tf32(pa[e], hi, lo);
                AsH[lrow][lc4 + e] = hi; AsL[lrow][lc4 + e] = lo;
                split_tf32(pb[e], hi, lo);
                BsH[lrow][lc4 + e] = hi; BsL[lrow][lc4 + e] = lo;
            }
        }
        __syncthreads();
        if (k0 + 16 < K) {
            av = *(const float4*)(Ap + k0 + 16);
            bv = *(const float4*)(Bp + k0 + 16);
        }
        #pragma unroll
        for (int ks = 0; ks < 16; ks += 8) {
            unsigned ah[2][4], al[2][4], bh[2][2], bl[2][2];
            #pragma unroll
            for (int mt = 0; mt < 2; mt++) {
                int r = wm * 32 + mt * 16 + g;
                ah[mt][0] = AsH[r    ][ks + c];     al[mt][0] = AsL[r    ][ks + c];
                ah[mt][1] = AsH[r + 8][ks + c];     al[mt][1] = AsL[r + 8][ks + c];
                ah[mt][2] = AsH[r    ][ks + c + 4]; al[mt][2] = AsL[r    ][ks + c + 4];
                ah[mt][3] = AsH[r + 8][ks + c + 4]; al[mt][3] = AsL[r + 8][ks + c + 4];
            }
            #pragma unroll
            for (int nt = 0; nt < 2; nt++) {
                int nn = wn * 16 + nt * 8 + g;
                bh[nt][0] = BsH[nn][ks + c];     bl[nt][0] = BsL[nn][ks + c];
                bh[nt][1] = BsH[nn][ks + c + 4]; bl[nt][1] = BsL[nn][ks + c + 4];
            }
            #pragma unroll
            for (int mt = 0; mt < 2; mt++)
                #pragma unroll
                for (int nt = 0; nt < 2; nt++) {
                    mma8(d[mt][nt], ah[mt], bh[nt]);
                    mma8(d[mt][nt], ah[mt], bl[nt]);
                    mma8(d[mt][nt], al[mt], bh[nt]);
                }
        }
    }
    #pragma unroll
    for (int mt = 0; mt < 2; mt++) {
        #pragma unroll
        for (int nt = 0; nt < 2; nt++) {
            int row0 = m0 + wm * 32 + mt * 16 + g;
            int col  = n0 + wn * 16 + nt * 8 + 2 * c;
            #pragma unroll
            for (int half = 0; half < 2; half++) {
                int m = row0 + half * 8;
                float v0 = d[mt][nt][half * 2 + 0] * scale;
                float v1 = d[mt][nt][half * 2 + 1] * scale;
                if (bias) { v0 += bias[col]; v1 += bias[col + 1]; }
                if (Cadd) {
                    v0 += Cadd[(long long)m * ldc + col];
                    v1 += Cadd[(long long)m * ldc + col + 1];
                }
                *(float2*)(C + (long long)m * ldc + col) = make_float2(v0, v1);
            }
        }
    }
}

// ---------------- elementwise (float4 vectorized) ----------------
__global__ void a1_kernel(const float4* __restrict__ P1, const float4* __restrict__ P2,
                          const float4* __restrict__ an, float4* __restrict__ o) {
    int i = blockIdx.x * 256 + threadIdx.x;
    float4 p1 = P1[i], p2 = P2[i], av = an[i], r;
    r.x = fsig(fmaf(p1.x, av.x, p2.x));
    r.y = fsig(fmaf(p1.y, av.y, p2.y));
    r.z = fsig(fmaf(p1.z, av.z, p2.z));
    r.w = fsig(fmaf(p1.w, av.w, p2.w));
    o[i] = r;
}
__global__ void final_kernel(const float4* __restrict__ SD, const float4* __restrict__ A2,
                             float4* __restrict__ o) {
    int i = blockIdx.x * 256 + threadIdx.x;
    float4 sd = SD[i], a2 = A2[i], r;
    r.x = fsig(sd.x) * a2.x;
    r.y = fsig(sd.y) * a2.y;
    r.z = fsig(sd.z) * a2.z;
    r.w = fsig(sd.w) * a2.w;
    o[i] = r;
}

// ---------------- row softmax stats ----------------
__global__ __launch_bounds__(256) void stats_kernel(const float* __restrict__ Sc,
                                                    float* __restrict__ Mo, float* __restrict__ Zi) {
    long long row = blockIdx.x;
    const float* p = Sc + row * 1024;
    int t = threadIdx.x;
    float4 v = *(const float4*)(p + t * 4);
    float mx = fmaxf(fmaxf(v.x, v.y), fmaxf(v.z, v.w));
    __shared__ float sh[8];
    #pragma unroll
    for (int o = 16; o; o >>= 1) mx = fmaxf(mx, __shfl_xor_sync(~0u, mx, o));
    if ((t & 31) == 0) sh[t >> 5] = mx;
    __syncthreads();
    if (t == 0) { float m = sh[0]; for (int i = 1; i < 8; i++) m = fmaxf(m, sh[i]); sh[0] = m; }
    __syncthreads();
    mx = sh[0];
    float sum = fexp(v.x - mx) + fexp(v.y - mx) + fexp(v.z - mx) + fexp(v.w - mx);
    #pragma unroll
    for (int o = 16; o; o >>= 1) sum += __shfl_xor_sync(~0u, sum, o);
    __syncthreads();
    if ((t & 31) == 0) sh[t >> 5] = sum;
    __syncthreads();
    if (t == 0) { float s = 0.f; for (int i = 0; i < 8; i++) s += sh[i]; Mo[row] = mx; Zi[row] = 1.f / s; }
}

// ---------------- AV via 3xTF32, pre-split hi/lo planes, 256 threads ----------------
// GO[j,c] = sig(g)*sum_x E[x,j]*Zi[x]*V[x,c]; A[m=j][k=x] = E, B[n=c][k=x] = V*Zi.
__global__ __launch_bounds__(256) void av_tf32(
    const float* __restrict__ Sc, const float* __restrict__ Mx, const float* __restrict__ Zi,
    const float* __restrict__ KVG, float* __restrict__ GO) {
    int h = blockIdx.y;
    int j0 = blockIdx.x * 64;
    const float* Sch = Sc + (long long)h * (1 << 20);
    const float* Mh  = Mx + (h << 10);
    const float* Zh  = Zi + (h << 10);
    const float* Vh  = KVG + (long long)h * 196608 + 64;
    const float* Gh  = KVG + (long long)h * 196608 + 128;
    float*       GOh = GO + (long long)h * 65536;
    __shared__ unsigned EsH[64][17], EsL[64][17];   // [j][x]
    __shared__ unsigned VsH[64][17], VsL[64][17];   // [c][x]
    int t = threadIdx.x;
    int lane = t & 31, wid = t >> 5;
    int wm = wid >> 2, wn = wid & 3;
    int g = lane >> 2, c = lane & 3;
    int xrow = t >> 4;                  // 0..15 (k index within tile)
    int jc4  = (t & 15) * 4;            // 0..60 (j / c index)
    const float* Scp = Sch + (long long)xrow * 1024 + j0 + jc4;
    const float* Vp  = Vh + (long long)xrow * 192 + jc4;
    float4 ev = *(const float4*)Scp;
    float4 vv = *(const float4*)Vp;
    float mreg = Mh[xrow], zreg = Zh[xrow];
    float d[2][2][4] = {};
    for (int x0 = 0; x0 < 1024; x0 += 16) {
        __syncthreads();
        {
            const float* pe = &ev.x;
            const float* pv = &vv.x;
            #pragma unroll
            for (int e = 0; e < 4; e++) {
                unsigned hi, lo;
                split_tf32(fexp(pe[e] - mreg), hi, lo);
                EsH[jc4 + e][xrow] = hi; EsL[jc4 + e][xrow] = lo;
                split_tf32(pv[e] * zreg, hi, lo);
                VsH[jc4 + e][xrow] = hi; VsL[jc4 + e][xrow] = lo;
            }
        }
        __syncthreads();
        if (x0 + 16 < 1024) {
            ev = *(const float4*)(Scp + (long long)(x0 + 16) * 1024);
            vv = *(const float4*)(Vp + (long long)(x0 + 16) * 192);
            mreg = Mh[x0 + 16 + xrow];
            zreg = Zh[x0 + 16 + xrow];
        }
        #pragma unroll
        for (int ks = 0; ks < 16; ks += 8) {
            unsigned ah[2][4], al[2][4], bh[2][2], bl[2][2];
            #pragma unroll
            for (int mt = 0; mt < 2; mt++) {
                int r = wm * 32 + mt * 16 + g;
                ah[mt][0] = EsH[r    ][ks + c];     al[mt][0] = EsL[r    ][ks + c];
                ah[mt][1] = EsH[r + 8][ks + c];     al[mt][1] = EsL[r + 8][ks + c];
                ah[mt][2] = EsH[r    ][ks + c + 4]; al[mt][2] = EsL[r    ][ks + c + 4];
                ah[mt][3] = EsH[r + 8][ks + c + 4]; al[mt][3] = EsL[r + 8][ks + c + 4];
            }
            #pragma unroll
            for (int nt = 0; nt < 2; nt++) {
                int nn = wn * 16 + nt * 8 + g;
                bh[nt][0] = VsH[nn][ks + c];     bl[nt][0] = VsL[nn][ks + c];
                bh[nt][1] = VsH[nn][ks + c + 4]; bl[nt][1] = VsL[nn][ks + c + 4];
            }
            #pragma unroll
            for (int mt = 0; mt < 2; mt++)
                #pragma unroll
                for (int nt = 0; nt < 2; nt++) {
                    mma8(d[mt][nt], ah[mt], bh[nt]);
                    mma8(d[mt][nt], ah[mt], bl[nt]);
                    mma8(d[mt][nt], al[mt], bh[nt]);
                }
        }
    }
    #pragma unroll
    for (int mt = 0; mt < 2; mt++) {
        #pragma unroll
        for (int nt = 0; nt < 2; nt++) {
            int j0r = j0 + wm * 32 + mt * 16 + g;
            int cc  = wn * 16 + nt * 8 + 2 * c;
            #pragma unroll
            for (int half = 0; half < 2; half++) {
                int j = j0r + half * 8;
                float g0 = fsig(Gh[(long long)j * 192 + cc]);
                float g1 = fsig(Gh[(long long)j * 192 + cc + 1]);
                float v0 = d[mt][nt][half * 2 + 0] * g0;
                float v1 = d[mt][nt][half * 2 + 1] * g1;
                *(float2*)(GOh + (long long)j * 64 + cc) = make_float2(v0, v1);
            }
        }
    }
}

// ---------------- driver ----------------
extern "C" void kernel_launch(void* const* d_in, const int* in_sizes, int n_in,
                              void* d_out, int out_size) {
    const float* a      = (const float*)d_in[0];
    const float* z      = (const float*)d_in[1];
    const float* s      = (const float*)d_in[2];
    const float* sn_w   = (const float*)d_in[3];
    const float* pb_w   = (const float*)d_in[4];
    const float* pb_b   = (const float*)d_in[5];
    const float* pn_w   = (const float*)d_in[6];
    const float* pnorm_w= (const float*)d_in[7];
    const float* pnorm_b= (const float*)d_in[8];
    const float* q_w    = (const float*)d_in[9];
    const float* q_b    = (const float*)d_in[10];
    const float* kvg_w  = (const float*)d_in[11];
    const float* bias_w = (const float*)d_in[12];
    const float* bias_b = (const float*)d_in[13];
    const float* attn_w = (const float*)d_in[14];
    const float* out_w  = (const float*)d_in[15];
    const float* out_b  = (const float*)d_in[16];
    float* out = (float*)d_out;

    float *an, *sn, *P1, *P2, *a1, *Q, *KVG, *Bm, *Sc, *Mx, *Zi, *GO, *A2, *SD;
    cudaGetSymbolAddress((void**)&an, d_an);
    cudaGetSymbolAddress((void**)&sn, d_sn);
    cudaGetSymbolAddress((void**)&P1, d_P1);
    cudaGetSymbolAddress((void**)&P2, d_P2);
    cudaGetSymbolAddress((void**)&a1, d_a1);
    cudaGetSymbolAddress((void**)&Q,  d_Q);
    cudaGetSymbolAddress((void**)&KVG,d_KVG);
    cudaGetSymbolAddress((void**)&Bm, d_B);
    cudaGetSymbolAddress((void**)&Sc, d_Sc);
    cudaGetSymbolAddress((void**)&Mx, d_M);
    cudaGetSymbolAddress((void**)&Zi, d_Zi);
    cudaGetSymbolAddress((void**)&GO, d_GO);
    cudaGetSymbolAddress((void**)&A2, d_A2);
    cudaGetSymbolAddress((void**)&SD, d_SD);

    // 1) LayerNorms
    ln_kernel<<<SS, 256>>>(a, nullptr, an, CA);
    ln_kernel<<<SS, 256>>>(s, sn_w,  sn, CS);

    // 2) P1 = sn@pb_w^T + pb_b ; P2 = sn@pn_w^T
    gemm_tf32<<<dim3(16,16,1), 256>>>(sn, CS, 0, pb_w, CS, 0, P1, CA, 0, pb_b, nullptr, 0, CS, 1.f);
    gemm_tf32<<<dim3(16,16,1), 256>>>(sn, CS, 0, pn_w, CS, 0, P2, CA, 0, nullptr, nullptr, 0, CS, 1.f);

    // 3) a1 = sigmoid(P1*an + P2)
    a1_kernel<<<1024, 256>>>((const float4*)P1, (const float4*)P2, (const float4*)an, (float4*)a1);

    // 4) Q and KVG projections
    gemm_tf32<<<dim3(16,16,1), 256>>>(a1, CA, 0, q_w,   CA, 0, Q,   CA,   0, q_b,    nullptr, 0, CA, 1.f);
    gemm_tf32<<<dim3(48,16,1), 256>>>(a1, CA, 0, kvg_w, CA, 0, KVG, 3*CA, 0, nullptr, nullptr, 0, CA, 1.f);

    // 5) pair bias from z (LN + projection), flat layout == [h,x,y]
    zbias_kernel<<<8192, 128>>>(z, pnorm_w, pnorm_b, bias_w, bias_b, Bm);

    // 6) scores Sc[h,x,y] = K[x]·Q[y]/64 + bias
    gemm_tf32<<<dim3(16,16,NH), 256>>>(KVG, 192, 196608, Q, 64, 65536,
                                       Sc, 1024, 1 << 20, nullptr, Bm, 1 << 20, 64, 1.f/64.f);

    // 7) softmax row stats
    stats_kernel<<<NH*SS, 256>>>(Sc, Mx, Zi);

    // 8) O = P^T V, gated by sigmoid(g); GO flat == [S,ca]
    av_tf32<<<dim3(16,16), 256>>>(Sc, Mx, Zi, KVG, GO);

    // 9) a2 = GO@attn_w^T ; SD = s@out_w^T + out_b
    gemm_tf32<<<dim3(16,16,1), 256>>>(GO, CA, 0, attn_w, CA, 0, A2, CA, 0, nullptr, nullptr, 0, CA, 1.f);
    gemm_tf32<<<dim3(16,16,1), 256>>>(s,  CS, 0, out_w,  CS, 0, SD, CA, 0, out_b,  nullptr, 0, CS, 1.f);

    // 10) out = sigmoid(SD) * a2
    final_kernel<<<1024, 256>>>((const float4*)SD, (const float4*)A2, (float4*)out);
}